// round 3
// baseline (speedup 1.0000x reference)
#include <cuda_runtime.h>

// Problem shape (fixed by the dataset)
#define Bn 8
#define Ln 4096
#define Mn 2048
#define Dn 512
#define CK 32              // chunk length along M
#define NC (Mn / CK)       // 64 chunks
#define D4 (Dn / 4)        // 128 float4 per row

// -------- device scratch (static globals: allocation-free) --------
__device__ float g_decay[Bn * Mn];        // per-chunk-slot decay (1.0 for invalid slots)
__device__ float g_pp[Bn * Mn];           // within-chunk inclusive prefix products of decay
__device__ float g_Ac[Bn * NC];           // per-chunk total decay product
__device__ float g_Bc[Bn * NC * Dn];      // per-chunk local scan result (h0 = 0)
__device__ float g_carry[Bn * NC * Dn];   // state entering each chunk
__device__ int   g_cidx[Bn * Ln];         // inclusive cumsum(token_mask) - 1  (>= -1)
__device__ float g_ema[Bn * Mn * Dn];     // local (h0=0) EMA states, all t
__device__ int   g_maskflag;              // 1 = mask stored as 1-byte, 0 = 4-byte ints

// -------- K0: detect token_mask element width --------
__global__ void k_detect(const unsigned char* __restrict__ mb,
                         const int* __restrict__ counts) {
    __shared__ int sred[8];
    int tid = threadIdx.x;
    int s = 0;
    for (int i = tid; i < Ln; i += 256) s += (mb[i] != 0);
    #pragma unroll
    for (int o = 16; o; o >>= 1) s += __shfl_down_sync(0xFFFFFFFFu, s, o);
    if ((tid & 31) == 0) sred[tid >> 5] = s;
    __syncthreads();
    if (tid == 0) {
        int t = 0;
        #pragma unroll
        for (int w = 0; w < 8; w++) t += sred[w];
        // u8 layout: nonzero bytes in first Ln bytes == counts[0] (1024..2048).
        // i32 layout: nonzero bytes among first Ln bytes <= 1024 trues of first
        // 1024 positions -> cannot match counts[0] in practice.
        g_maskflag = (t == counts[0]) ? 1 : 0;
    }
}

// -------- K1: per-batch compaction (decay row + per-token chunk index) --------
__global__ __launch_bounds__(512) void k_prep(const float* __restrict__ prob,
                                              const void* __restrict__ maskbuf) {
    const int b   = blockIdx.x;
    const int tid = threadIdx.x;           // 512 threads, 8 tokens each
    const unsigned char* mb8  = (const unsigned char*)maskbuf;
    const int*           mb32 = (const int*)maskbuf;
    const int flag = g_maskflag;

    int m[8];
    int s = 0;
    const int base = tid * 8;
    #pragma unroll
    for (int j = 0; j < 8; j++) {
        int l = base + j;
        int v = flag ? (mb8[b * Ln + l] != 0) : (mb32[b * Ln + l] != 0);
        m[j] = v;
        s += v;
    }

    // block-wide exclusive scan of per-thread counts
    const int lane = tid & 31, wid = tid >> 5;
    int inc = s;
    #pragma unroll
    for (int o = 1; o < 32; o <<= 1) {
        int n = __shfl_up_sync(0xFFFFFFFFu, inc, o);
        if (lane >= o) inc += n;
    }
    __shared__ int wsum[16];
    if (lane == 31) wsum[wid] = inc;
    __syncthreads();
    if (wid == 0 && lane < 16) {
        int v = wsum[lane];
        #pragma unroll
        for (int o = 1; o < 16; o <<= 1) {
            int n = __shfl_up_sync(0x0000FFFFu, v, o);
            if (lane >= o) v += n;
        }
        wsum[lane] = v;
    }
    __syncthreads();
    const int excl = inc - s + ((wid > 0) ? wsum[wid - 1] : 0);

    // init decay row to 1.0 (invalid slots: decay=1 -> state carries, matches ref)
    for (int i = tid; i < Mn; i += 512) g_decay[b * Mn + i] = 1.0f;
    __syncthreads();

    int run = excl;
    #pragma unroll
    for (int j = 0; j < 8; j++) {
        const int l = base + j;
        if (m[j]) {
            float p = prob[b * Ln + l];
            float dcy = fminf(fmaxf(1.0f - p, 0.0f), 1.0f);
            g_decay[b * Mn + run] = dcy;
            run++;
        }
        g_cidx[b * Ln + l] = run - 1;
    }
}

// -------- K2: per-chunk local EMA scan (h0 = 0), prefix products, A_c, B_c --------
__global__ __launch_bounds__(128) void k_scan(const float4* __restrict__ hidden) {
    const int blk = blockIdx.x;            // b*NC + c
    const int b = blk / NC, c = blk % NC;
    const int tid = threadIdx.x;           // 128 threads = one float4 column each

    __shared__ float sd[CK], sod[CK];
    if (tid < CK) {
        float d = g_decay[b * Mn + c * CK + tid];
        sd[tid]  = d;
        sod[tid] = 1.0f - d;
    }
    __syncthreads();

    if (tid == 0) {
        float p = 1.0f;
        #pragma unroll
        for (int t = 0; t < CK; t++) {
            p *= sd[t];
            g_pp[b * Mn + c * CK + t] = p;
        }
        g_Ac[blk] = p;
    }

    const size_t rowbase = (size_t)(b * Mn + c * CK) * D4 + tid;
    const float4* src = hidden + rowbase;
    float4*       dst = ((float4*)g_ema) + rowbase;

    // depth-8 prefetch ring: keeps 8 LDG.128 in flight per thread
    float4 buf[8];
    #pragma unroll
    for (int i = 0; i < 8; i++) buf[i] = src[(size_t)i * D4];

    float4 h = make_float4(0.f, 0.f, 0.f, 0.f);
    #pragma unroll
    for (int t = 0; t < CK; t++) {
        float4 x = buf[t & 7];
        if (t + 8 < CK) buf[t & 7] = src[(size_t)(t + 8) * D4];
        const float d = sd[t], od = sod[t];
        h.x = fmaf(d, h.x, od * x.x);
        h.y = fmaf(d, h.y, od * x.y);
        h.z = fmaf(d, h.z, od * x.z);
        h.w = fmaf(d, h.w, od * x.w);
        dst[(size_t)t * D4] = h;
    }
    ((float4*)g_Bc)[(size_t)blk * D4 + tid] = h;
}

// -------- K3: sequential chunk-carry combine + new_state --------
__global__ __launch_bounds__(256) void k_carry(const float* __restrict__ state,
                                               const int* __restrict__ counts,
                                               float* __restrict__ out_ns) {
    const int idx = blockIdx.x * blockDim.x + threadIdx.x;
    if (idx >= Bn * Dn) return;
    const int b = idx / Dn, d = idx % Dn;

    float carry = state[idx];
    #pragma unroll
    for (int c = 0; c < NC; c++) {
        g_carry[(size_t)(b * NC + c) * Dn + d] = carry;
        carry = fmaf(g_Ac[b * NC + c], carry, g_Bc[(size_t)(b * NC + c) * Dn + d]);
    }

    if (out_ns) {
        const int cnt = counts[b];
        float ns;
        if (cnt > 0) {
            const int t = cnt - 1, cl = t / CK;
            ns = g_ema[(size_t)(b * Mn + t) * Dn + d] +
                 g_pp[b * Mn + t] * g_carry[(size_t)(b * NC + cl) * Dn + d];
        } else {
            ns = state[idx];
        }
        out_ns[idx] = ns;
    }
}

// -------- K4: gather + carry fix-up + residual add --------
__global__ __launch_bounds__(256) void k_out(const float4* __restrict__ residual,
                                             float4* __restrict__ out) {
    const int row = blockIdx.x * 2 + (threadIdx.x >> 7);  // (b*Ln + l)
    const int t   = threadIdx.x & 127;
    const int b   = row / Ln;
    const int ci  = g_cidx[row];

    const size_t o = (size_t)row * D4 + t;
    float4 r = residual[o];
    float4 v = r;
    if (ci >= 0) {
        const float pp = g_pp[b * Mn + ci];
        const int   cc = ci / CK;
        float4 e  = ((const float4*)g_ema)[(size_t)(b * Mn + ci) * D4 + t];
        float4 cr = ((const float4*)g_carry)[(size_t)(b * NC + cc) * D4 + t];
        v.x = r.x + fmaf(pp, cr.x, e.x);
        v.y = r.y + fmaf(pp, cr.y, e.y);
        v.z = r.z + fmaf(pp, cr.z, e.z);
        v.w = r.w + fmaf(pp, cr.w, e.w);
    }
    out[o] = v;
}

extern "C" void kernel_launch(void* const* d_in, const int* in_sizes, int n_in,
                              void* d_out, int out_size) {
    const float* hidden   = (const float*)d_in[0];  // (B,M,D)
    const float* residual = (const float*)d_in[1];  // (B,L,D)
    const float* prob     = (const float*)d_in[2];  // (B,L)
    const float* state    = (const float*)d_in[3];  // (B,D)
    const void*  mask     = d_in[4];                // (B,L) bool (width auto-detected)
    const int*   counts   = (const int*)d_in[5];    // (B,)

    float* out = (float*)d_out;
    const long long main_elems = (long long)Bn * Ln * Dn;
    float* ns = (out_size >= main_elems + Bn * Dn) ? (out + main_elems) : nullptr;

    k_detect<<<1, 256>>>((const unsigned char*)mask, counts);
    k_prep  <<<Bn, 512>>>(prob, mask);
    k_scan  <<<Bn * NC, 128>>>((const float4*)hidden);
    k_carry <<<(Bn * Dn + 255) / 256, 256>>>(state, counts, ns);
    k_out   <<<Bn * Ln / 2, 256>>>((const float4*)residual, (float4*)out);
}

// round 4
// speedup vs baseline: 1.2730x; 1.2730x over previous
#include <cuda_runtime.h>

// Problem shape (fixed by the dataset)
#define Bn 8
#define Ln 4096
#define Mn 2048
#define Dn 512
#define CK 32              // chunk length along M
#define NC (Mn / CK)       // 64 chunks
#define D4 (Dn / 4)        // 128 float4 per row

// -------- device scratch (static globals: allocation-free) --------
__device__ float g_decay[Bn * Mn];        // per-chunk-slot decay (1.0 for invalid slots)
__device__ float g_pp[Bn * Mn];           // within-chunk inclusive prefix products of decay
__device__ float g_Ac[Bn * NC];           // per-chunk total decay product
__device__ float g_Bc[Bn * NC * Dn];      // per-chunk local scan result (h0 = 0)
__device__ float g_carry[Bn * NC * Dn];   // state entering each chunk
__device__ int   g_cidx[Bn * Ln];         // inclusive cumsum(token_mask) - 1  (>= -1)
__device__ float g_ema[Bn * Mn * Dn];     // local (h0=0) EMA states, all t
__device__ int   g_maskflag;              // 1 = mask stored as 1-byte, 0 = 4-byte ints

// -------- K0: detect token_mask element width --------
__global__ void k_detect(const unsigned char* __restrict__ mb,
                         const int* __restrict__ counts) {
    __shared__ int sred[8];
    int tid = threadIdx.x;
    int s = 0;
    for (int i = tid; i < Ln; i += 256) s += (mb[i] != 0);
    #pragma unroll
    for (int o = 16; o; o >>= 1) s += __shfl_down_sync(0xFFFFFFFFu, s, o);
    if ((tid & 31) == 0) sred[tid >> 5] = s;
    __syncthreads();
    if (tid == 0) {
        int t = 0;
        #pragma unroll
        for (int w = 0; w < 8; w++) t += sred[w];
        // u8 layout: nonzero bytes in first Ln bytes == counts[0] (1024..2048).
        // i32 layout: nonzero bytes among first Ln bytes <= 1024 -> cannot match.
        g_maskflag = (t == counts[0]) ? 1 : 0;
    }
}

// -------- K1: per-batch compaction (decay row + per-token chunk index) --------
__global__ __launch_bounds__(512) void k_prep(const float* __restrict__ prob,
                                              const void* __restrict__ maskbuf) {
    const int b   = blockIdx.x;
    const int tid = threadIdx.x;           // 512 threads, 8 tokens each
    const unsigned char* mb8  = (const unsigned char*)maskbuf;
    const int*           mb32 = (const int*)maskbuf;
    const int flag = g_maskflag;

    int m[8];
    int s = 0;
    const int base = tid * 8;
    #pragma unroll
    for (int j = 0; j < 8; j++) {
        int l = base + j;
        int v = flag ? (mb8[b * Ln + l] != 0) : (mb32[b * Ln + l] != 0);
        m[j] = v;
        s += v;
    }

    // block-wide exclusive scan of per-thread counts
    const int lane = tid & 31, wid = tid >> 5;
    int inc = s;
    #pragma unroll
    for (int o = 1; o < 32; o <<= 1) {
        int n = __shfl_up_sync(0xFFFFFFFFu, inc, o);
        if (lane >= o) inc += n;
    }
    __shared__ int wsum[16];
    if (lane == 31) wsum[wid] = inc;
    __syncthreads();
    if (wid == 0 && lane < 16) {
        int v = wsum[lane];
        #pragma unroll
        for (int o = 1; o < 16; o <<= 1) {
            int n = __shfl_up_sync(0x0000FFFFu, v, o);
            if (lane >= o) v += n;
        }
        wsum[lane] = v;
    }
    __syncthreads();
    const int excl = inc - s + ((wid > 0) ? wsum[wid - 1] : 0);

    // init decay row to 1.0 (invalid slots: decay=1 -> state carries, matches ref)
    for (int i = tid; i < Mn; i += 512) g_decay[b * Mn + i] = 1.0f;
    __syncthreads();

    int run = excl;
    #pragma unroll
    for (int j = 0; j < 8; j++) {
        const int l = base + j;
        if (m[j]) {
            float p = prob[b * Ln + l];
            float dcy = fminf(fmaxf(1.0f - p, 0.0f), 1.0f);
            g_decay[b * Mn + run] = dcy;
            run++;
        }
        g_cidx[b * Ln + l] = run - 1;
    }
}

// -------- K2: per-chunk local EMA scan (h0 = 0), prefix products, A_c, B_c --------
__global__ __launch_bounds__(128) void k_scan(const float4* __restrict__ hidden) {
    const int blk = blockIdx.x;            // b*NC + c
    const int b = blk / NC, c = blk % NC;
    const int tid = threadIdx.x;           // 128 threads = one float4 column each

    __shared__ float sd[CK], sod[CK];
    if (tid < CK) {
        float d = g_decay[b * Mn + c * CK + tid];
        sd[tid]  = d;
        sod[tid] = 1.0f - d;
    }
    __syncthreads();

    if (tid == 0) {
        float p = 1.0f;
        #pragma unroll
        for (int t = 0; t < CK; t++) {
            p *= sd[t];
            g_pp[b * Mn + c * CK + t] = p;
        }
        g_Ac[blk] = p;
    }

    const size_t rowbase = (size_t)(b * Mn + c * CK) * D4 + tid;
    const float4* src = hidden + rowbase;
    float4*       dst = ((float4*)g_ema) + rowbase;

    // depth-8 prefetch ring: keeps 8 LDG.128 in flight per thread
    float4 buf[8];
    #pragma unroll
    for (int i = 0; i < 8; i++) buf[i] = src[(size_t)i * D4];

    float4 h = make_float4(0.f, 0.f, 0.f, 0.f);
    #pragma unroll
    for (int t = 0; t < CK; t++) {
        float4 x = buf[t & 7];
        if (t + 8 < CK) buf[t & 7] = src[(size_t)(t + 8) * D4];
        const float d = sd[t], od = sod[t];
        h.x = fmaf(d, h.x, od * x.x);
        h.y = fmaf(d, h.y, od * x.y);
        h.z = fmaf(d, h.z, od * x.z);
        h.w = fmaf(d, h.w, od * x.w);
        dst[(size_t)t * D4] = h;
    }
    ((float4*)g_Bc)[(size_t)blk * D4 + tid] = h;
}

// -------- K3: sequential chunk-carry combine + new_state --------
// 128-thread blocks: each block is a single batch row (Dn/128 = 4 blocks per b),
// Ac staged in shared, Bc streamed through a depth-16 register prefetch ring so
// the dependent chain is 64 FMAs instead of 64 exposed memory latencies.
__global__ __launch_bounds__(128) void k_carry(const float* __restrict__ state,
                                               const int* __restrict__ counts,
                                               float* __restrict__ out_ns) {
    const int idx = blockIdx.x * 128 + threadIdx.x;   // (b,d) flat
    const int b = idx >> 9;          // / Dn
    const int d = idx & (Dn - 1);    // % Dn

    __shared__ float sA[NC];
    if (threadIdx.x < NC) sA[threadIdx.x] = g_Ac[b * NC + threadIdx.x];
    __syncthreads();

    const float* Bc = g_Bc    + (size_t)b * NC * Dn + d;
    float*       Cr = g_carry + (size_t)b * NC * Dn + d;

    float buf[16];
    #pragma unroll
    for (int i = 0; i < 16; i++) buf[i] = Bc[(size_t)i * Dn];

    float carry = state[idx];
    #pragma unroll
    for (int c = 0; c < NC; c++) {
        Cr[(size_t)c * Dn] = carry;
        const float bc = buf[c & 15];
        if (c + 16 < NC) buf[c & 15] = Bc[(size_t)(c + 16) * Dn];
        carry = fmaf(sA[c], carry, bc);
    }

    if (out_ns) {
        const int cnt = counts[b];
        float ns;
        if (cnt > 0) {
            const int t = cnt - 1, cl = t / CK;
            ns = g_ema[(size_t)(b * Mn + t) * Dn + d] +
                 g_pp[b * Mn + t] * g_carry[(size_t)(b * NC + cl) * Dn + d];
        } else {
            ns = state[idx];
        }
        out_ns[idx] = ns;
    }
}

// -------- K4: gather + carry fix-up + residual add --------
__global__ __launch_bounds__(256) void k_out(const float4* __restrict__ residual,
                                             float4* __restrict__ out) {
    const int row = blockIdx.x * 2 + (threadIdx.x >> 7);  // (b*Ln + l)
    const int t   = threadIdx.x & 127;
    const int b   = row / Ln;
    const int ci  = g_cidx[row];

    const size_t o = (size_t)row * D4 + t;
    float4 r = residual[o];
    float4 v = r;
    if (ci >= 0) {
        const float pp = g_pp[b * Mn + ci];
        const int   cc = ci / CK;
        float4 e  = ((const float4*)g_ema)[(size_t)(b * Mn + ci) * D4 + t];
        float4 cr = ((const float4*)g_carry)[(size_t)(b * NC + cc) * D4 + t];
        v.x = r.x + fmaf(pp, cr.x, e.x);
        v.y = r.y + fmaf(pp, cr.y, e.y);
        v.z = r.z + fmaf(pp, cr.z, e.z);
        v.w = r.w + fmaf(pp, cr.w, e.w);
    }
    out[o] = v;
}

extern "C" void kernel_launch(void* const* d_in, const int* in_sizes, int n_in,
                              void* d_out, int out_size) {
    const float* hidden   = (const float*)d_in[0];  // (B,M,D)
    const float* residual = (const float*)d_in[1];  // (B,L,D)
    const float* prob     = (const float*)d_in[2];  // (B,L)
    const float* state    = (const float*)d_in[3];  // (B,D)
    const void*  mask     = d_in[4];                // (B,L) bool (width auto-detected)
    const int*   counts   = (const int*)d_in[5];    // (B,)

    float* out = (float*)d_out;
    const long long main_elems = (long long)Bn * Ln * Dn;
    float* ns = (out_size >= main_elems + Bn * Dn) ? (out + main_elems) : nullptr;

    k_detect<<<1, 256>>>((const unsigned char*)mask, counts);
    k_prep  <<<Bn, 512>>>(prob, mask);
    k_scan  <<<Bn * NC, 128>>>((const float4*)hidden);
    k_carry <<<Bn * Dn / 128, 128>>>(state, counts, ns);
    k_out   <<<Bn * Ln / 2, 256>>>((const float4*)residual, (float4*)out);
}